// round 12
// baseline (speedup 1.0000x reference)
#include <cuda_runtime.h>
#include <cstdint>
#include <cstddef>

#define D     128
#define HID   64
#define TOPK  50
#define PMAX  2048
#define MPAD  100096   /* 782 * 128 */
#define NSAMP 8192
#define CAP   4096

// Scratch (device globals — no runtime allocation allowed)
__device__ float g_sim[(size_t)PMAX * MPAD];
__device__ float g_logits[PMAX];

// ---------------------------------------------------------------------------
// FP32 SGEMM screen: sim[p][n] = sum_k A[p][k] * B[n][k]
// ---------------------------------------------------------------------------
__global__ __launch_bounds__(256, 2)
void gemm_kernel(const float* __restrict__ A, const float* __restrict__ B,
                 int P, int M) {
    __shared__ float As[2][16][128];
    __shared__ float Bs[2][16][128];

    const int tid = threadIdx.x;
    const int bm  = blockIdx.y * 128;
    const int bn  = blockIdx.x * 128;
    const int tx  = tid & 15;
    const int ty  = tid >> 4;
    const int lr  = tid >> 2;
    const int lc  = (tid & 3) << 2;

    const float* Aptr = A + (size_t)(bm + lr) * D + lc;
    const int n0 = bn + lr;
    const int n1 = bn + lr + 64;

    float4 ra0, ra1, rb0, rb1;
    const float4 fz = make_float4(0.f, 0.f, 0.f, 0.f);

    ra0 = *(const float4*)(Aptr);
    ra1 = *(const float4*)(Aptr + (size_t)64 * D);
    rb0 = (n0 < M) ? *(const float4*)(B + (size_t)n0 * D + lc) : fz;
    rb1 = (n1 < M) ? *(const float4*)(B + (size_t)n1 * D + lc) : fz;

    As[0][lc+0][lr]    = ra0.x; As[0][lc+1][lr]    = ra0.y;
    As[0][lc+2][lr]    = ra0.z; As[0][lc+3][lr]    = ra0.w;
    As[0][lc+0][lr+64] = ra1.x; As[0][lc+1][lr+64] = ra1.y;
    As[0][lc+2][lr+64] = ra1.z; As[0][lc+3][lr+64] = ra1.w;
    Bs[0][lc+0][lr]    = rb0.x; Bs[0][lc+1][lr]    = rb0.y;
    Bs[0][lc+2][lr]    = rb0.z; Bs[0][lc+3][lr]    = rb0.w;
    Bs[0][lc+0][lr+64] = rb1.x; Bs[0][lc+1][lr+64] = rb1.y;
    Bs[0][lc+2][lr+64] = rb1.z; Bs[0][lc+3][lr+64] = rb1.w;
    __syncthreads();

    float acc[8][8];
    #pragma unroll
    for (int i = 0; i < 8; ++i)
        #pragma unroll
        for (int j = 0; j < 8; ++j) acc[i][j] = 0.f;

    #pragma unroll
    for (int kt = 0; kt < 8; ++kt) {
        const int cur = kt & 1;
        if (kt < 7) {
            const int k0 = (kt + 1) * 16;
            ra0 = *(const float4*)(Aptr + k0);
            ra1 = *(const float4*)(Aptr + (size_t)64 * D + k0);
            rb0 = (n0 < M) ? *(const float4*)(B + (size_t)n0 * D + lc + k0) : fz;
            rb1 = (n1 < M) ? *(const float4*)(B + (size_t)n1 * D + lc + k0) : fz;
        }
        #pragma unroll
        for (int k = 0; k < 16; ++k) {
            float a[8], b[8];
            *(float4*)(a)     = *(const float4*)&As[cur][k][ty * 8];
            *(float4*)(a + 4) = *(const float4*)&As[cur][k][ty * 8 + 4];
            *(float4*)(b)     = *(const float4*)&Bs[cur][k][tx * 8];
            *(float4*)(b + 4) = *(const float4*)&Bs[cur][k][tx * 8 + 4];
            #pragma unroll
            for (int i = 0; i < 8; ++i)
                #pragma unroll
                for (int j = 0; j < 8; ++j)
                    acc[i][j] = fmaf(a[i], b[j], acc[i][j]);
        }
        if (kt < 7) {
            const int nxt = cur ^ 1;
            As[nxt][lc+0][lr]    = ra0.x; As[nxt][lc+1][lr]    = ra0.y;
            As[nxt][lc+2][lr]    = ra0.z; As[nxt][lc+3][lr]    = ra0.w;
            As[nxt][lc+0][lr+64] = ra1.x; As[nxt][lc+1][lr+64] = ra1.y;
            As[nxt][lc+2][lr+64] = ra1.z; As[nxt][lc+3][lr+64] = ra1.w;
            Bs[nxt][lc+0][lr]    = rb0.x; Bs[nxt][lc+1][lr]    = rb0.y;
            Bs[nxt][lc+2][lr]    = rb0.z; Bs[nxt][lc+3][lr]    = rb0.w;
            Bs[nxt][lc+0][lr+64] = rb1.x; Bs[nxt][lc+1][lr+64] = rb1.y;
            Bs[nxt][lc+2][lr+64] = rb1.z; Bs[nxt][lc+3][lr+64] = rb1.w;
            __syncthreads();
        }
    }

    #pragma unroll
    for (int i = 0; i < 8; ++i) {
        float* dst = g_sim + (size_t)(bm + ty * 8 + i) * MPAD + bn + tx * 8;
        *(float4*)(dst)     = make_float4(acc[i][0], acc[i][1], acc[i][2], acc[i][3]);
        *(float4*)(dst + 4) = make_float4(acc[i][4], acc[i][5], acc[i][6], acc[i][7]);
    }
}

// ---------------------------------------------------------------------------
// BF16x9 helpers: exact RN bf16 triple split (8+8+8 bits covers fp32 mantissa)
// ---------------------------------------------------------------------------
__device__ __forceinline__ float bf16_rn(float f) {
    unsigned int u = __float_as_uint(f);
    u = (u + 0x7FFFu + ((u >> 16) & 1u)) & 0xFFFF0000u;
    return __uint_as_float(u);
}
__device__ __forceinline__ void bf16_split3(float f, float& h, float& m, float& l) {
    h = bf16_rn(f);
    const float r1 = __fsub_rn(f, h);
    m = bf16_rn(r1);
    l = bf16_rn(__fsub_rn(r1, m));
}

__device__ __forceinline__ unsigned int fkey(float f) {
    unsigned int u = __float_as_uint(f);
    return (u & 0x80000000u) ? ~u : (u | 0x80000000u);
}

// ---------------------------------------------------------------------------
// Per-row top-K selection (one CTA per row)
// Screen with fast fp32 sim; rank candidates by bf16x9 emulation:
//   - 9 pass sums (A-split i x B-split j) computed EXACTLY (f64 over all
//     K=128; products exact, accumulation error ~1e-9 rel => no chunk noise)
//   - each pass sum cast to f32 with ONE RN
//   - final combine in DESCENDING significance order
//       hh, hm, hl, mh, mm, ml, lh, lm, ll
//     one RN per add — the component experimentally correlated with the
//     reference's realization (R10 resolved the contested pair with this
//     combine; R11 lost it when the combine went ascending).
// ---------------------------------------------------------------------------
__global__ __launch_bounds__(256)
void select_kernel(const float* __restrict__ X, const float* __restrict__ B,
                   int P, int M, float* __restrict__ out) {
    __shared__ unsigned int s_keys[CAP];
    __shared__ int s_idx[CAP];
    __shared__ float sxs[3][D];   // A splits: [0]=h, [1]=m, [2]=l
    __shared__ int s_cnt;
    __shared__ int s_tot;
    __shared__ unsigned long long s_red[256];

    const int p   = blockIdx.x;
    const int tid = threadIdx.x;
    const float* __restrict__ row = g_sim + (size_t)p * MPAD;

    if (tid < D) {
        float h, m, l;
        bf16_split3(X[(size_t)p * D + tid], h, m, l);
        sxs[0][tid] = h; sxs[1][tid] = m; sxs[2][tid] = l;
    }

    // --- deterministic strided sample ---
    int step = M / NSAMP; if (step < 1) step = 1;
    unsigned int samp[NSAMP / 256];
    #pragma unroll
    for (int t = 0; t < NSAMP / 256; ++t) {
        long long j = (long long)(tid + t * 256) * step;
        if (j >= M) j = M - 1;
        samp[t] = fkey(row[j]);
    }

    // --- binary search for the sample's TOPK-th largest screen key ---
    unsigned int thr = 0u;
    for (int bit = 31; bit >= 0; --bit) {
        const unsigned int cand = thr | (1u << bit);
        if (tid == 0) s_tot = 0;
        __syncthreads();
        int local = 0;
        #pragma unroll
        for (int t = 0; t < NSAMP / 256; ++t) local += (samp[t] >= cand);
        #pragma unroll
        for (int o = 16; o; o >>= 1) local += __shfl_down_sync(0xffffffffu, local, o);
        if ((tid & 31) == 0) atomicAdd(&s_tot, local);
        __syncthreads();
        if (s_tot >= TOPK) thr = cand;
        __syncthreads();
    }

    // --- collect candidates (margin vs top-50 is units; screen noise ~1e-4) ---
    if (tid == 0) s_cnt = 0;
    __syncthreads();
    for (int n = tid; n < M; n += 256) {
        const unsigned int k = fkey(row[n]);
        if (k >= thr) {
            const int pos = atomicAdd(&s_cnt, 1);
            if (pos < CAP) { s_keys[pos] = k; s_idx[pos] = n; }
        }
    }
    __syncthreads();
    const int cnt = (s_cnt < CAP) ? s_cnt : CAP;

    // --- refine: bf16x9, exact pass sums + descending f32 combine ---
    for (int i = tid; i < cnt; i += 256) {
        const float* __restrict__ brow = B + (size_t)s_idx[i] * D;
        double S[9];
        #pragma unroll
        for (int q = 0; q < 9; ++q) S[q] = 0.0;

        for (int kk = 0; kk < D; ++kk) {
            float bh, bm, bl;
            bf16_split3(__ldg(&brow[kk]), bh, bm, bl);
            const double xh = (double)sxs[0][kk];
            const double xm = (double)sxs[1][kk];
            const double xl = (double)sxs[2][kk];
            S[0] = fma(xh, (double)bh, S[0]);   // hh
            S[1] = fma(xh, (double)bm, S[1]);   // hm
            S[2] = fma(xh, (double)bl, S[2]);   // hl
            S[3] = fma(xm, (double)bh, S[3]);   // mh
            S[4] = fma(xm, (double)bm, S[4]);   // mm
            S[5] = fma(xm, (double)bl, S[5]);   // ml
            S[6] = fma(xl, (double)bh, S[6]);   // lh
            S[7] = fma(xl, (double)bm, S[7]);   // lm
            S[8] = fma(xl, (double)bl, S[8]);   // ll
        }
        // one RN per pass (f64 -> f32 cast), then descending combine, one RN per add
        float acc = (float)S[0];                      // hh
        acc = __fadd_rn(acc, (float)S[1]);            // hm
        acc = __fadd_rn(acc, (float)S[2]);            // hl
        acc = __fadd_rn(acc, (float)S[3]);            // mh
        acc = __fadd_rn(acc, (float)S[4]);            // mm
        acc = __fadd_rn(acc, (float)S[5]);            // ml
        acc = __fadd_rn(acc, (float)S[6]);            // lh
        acc = __fadd_rn(acc, (float)S[7]);            // lm
        acc = __fadd_rn(acc, (float)S[8]);            // ll
        s_keys[i] = fkey(acc);
    }
    __syncthreads();

    // --- iterative argmax: (value desc, index asc) matches stable top_k ---
    for (int k = 0; k < TOPK; ++k) {
        unsigned long long best = 0ull;
        for (int i = tid; i < cnt; i += 256) {
            const unsigned long long v =
                ((unsigned long long)s_keys[i] << 32) | (unsigned int)(~s_idx[i]);
            if (v > best) best = v;
        }
        s_red[tid] = best;
        __syncthreads();
        #pragma unroll
        for (int s = 128; s > 0; s >>= 1) {
            if (tid < s && s_red[tid + s] > s_red[tid]) s_red[tid] = s_red[tid + s];
            __syncthreads();
        }
        const unsigned long long w = s_red[0];
        for (int i = tid; i < cnt; i += 256) {
            const unsigned long long v =
                ((unsigned long long)s_keys[i] << 32) | (unsigned int)(~s_idx[i]);
            if (v == w) s_keys[i] = 0u;
        }
        if (tid == 0) {
            const int idx = (int)(~(unsigned int)w);
            out[(size_t)p * TOPK + k] = (float)idx;
            out[(size_t)P * TOPK + (size_t)p * TOPK + k] = (float)p;
        }
        __syncthreads();
    }
}

// ---------------------------------------------------------------------------
// Pooling: logits = relu(X @ W1 + b1) @ W2 + b2
// ---------------------------------------------------------------------------
__global__ __launch_bounds__(256)
void logits_kernel(const float* __restrict__ X, const float* __restrict__ W1,
                   const float* __restrict__ b1, const float* __restrict__ W2,
                   const float* __restrict__ b2, int P) {
    __shared__ float sx[16][128];
    const int tid = threadIdx.x;
    const int p0  = blockIdx.x * 16;

    for (int i = tid; i < 16 * 128 && p0 * 128 + i < P * 128; i += 256)
        sx[i / 128][i % 128] = X[(size_t)p0 * 128 + i];
    __syncthreads();

    const int warp = tid >> 5, lane = tid & 31;
    for (int pi = warp; pi < 16 && p0 + pi < P; pi += 8) {
        float h0 = b1[lane], h1 = b1[lane + 32];
        const float* x = sx[pi];
        #pragma unroll
        for (int i = 0; i < 128; ++i) {
            const float xi = x[i];
            h0 = fmaf(xi, W1[i * HID + lane],      h0);
            h1 = fmaf(xi, W1[i * HID + lane + 32], h1);
        }
        float v = fmaxf(h0, 0.f) * W2[lane] + fmaxf(h1, 0.f) * W2[lane + 32];
        #pragma unroll
        for (int o = 16; o; o >>= 1) v += __shfl_down_sync(0xffffffffu, v, o);
        if (lane == 0) g_logits[p0 + pi] = v + b2[0];
    }
}

// Softmax over patches + weighted sum + L2 normalize (single CTA)
__global__ __launch_bounds__(256)
void pool_kernel(const float* __restrict__ X, int P, float* __restrict__ outg) {
    __shared__ float sw[PMAX];
    __shared__ float sg[128];
    __shared__ float sred[256];
    const int tid = threadIdx.x;

    float m = -3.4e38f;
    for (int p = tid; p < P; p += 256) m = fmaxf(m, g_logits[p]);
    sred[tid] = m; __syncthreads();
    #pragma unroll
    for (int s = 128; s > 0; s >>= 1) {
        if (tid < s) sred[tid] = fmaxf(sred[tid], sred[tid + s]);
        __syncthreads();
    }
    const float mx = sred[0]; __syncthreads();

    float lsum = 0.f;
    for (int p = tid; p < P; p += 256) {
        const float e = expf(g_logits[p] - mx);
        sw[p] = e; lsum += e;
    }
    sred[tid] = lsum; __syncthreads();
    #pragma unroll
    for (int s = 128; s > 0; s >>= 1) {
        if (tid < s) sred[tid] += sred[tid + s];
        __syncthreads();
    }
    const float tot = sred[0]; __syncthreads();

    float g = 0.f;
    if (tid < 128) {
        for (int p = 0; p < P; ++p) g = fmaf(sw[p], X[(size_t)p * D + tid], g);
        g /= tot;
        sg[tid]  = g;
        sred[tid] = g * g;
    } else {
        sred[tid] = 0.f;
    }
    __syncthreads();
    #pragma unroll
    for (int s = 128; s > 0; s >>= 1) {
        if (tid < s) sred[tid] += sred[tid + s];
        __syncthreads();
    }
    const float nrm = sqrtf(sred[0]);
    if (tid < 128) outg[tid] = sg[tid] / fmaxf(nrm, 1e-12f);
}

// ---------------------------------------------------------------------------
extern "C" void kernel_launch(void* const* d_in, const int* in_sizes, int n_in,
                              void* d_out, int out_size) {
    const float* X  = (const float*)d_in[0];
    const float* B  = (const float*)d_in[1];
    const float* W1 = (const float*)d_in[2];
    const float* b1 = (const float*)d_in[3];
    const float* W2 = (const float*)d_in[4];
    const float* b2 = (const float*)d_in[5];
    float* out = (float*)d_out;

    const int P = in_sizes[0] / D;
    const int M = in_sizes[1] / D;

    dim3 ggrid((M + 127) / 128, P / 128);
    gemm_kernel<<<ggrid, 256>>>(X, B, P, M);
    select_kernel<<<P, 256>>>(X, B, P, M, out);
    logits_kernel<<<(P + 15) / 16, 256>>>(X, W1, b1, W2, b2, P);
    pool_kernel<<<1, 256>>>(X, P, out + (size_t)2 * P * TOPK);
}

// round 13
// speedup vs baseline: 1.2459x; 1.2459x over previous
#include <cuda_runtime.h>
#include <cstdint>
#include <cstddef>

#define D     128
#define HID   64
#define TOPK  50
#define PMAX  2048
#define MPAD  100096   /* 782 * 128 */
#define NSAMP 8192
#define CAP   4096

// Scratch (device globals — no runtime allocation allowed)
__device__ float g_sim[(size_t)PMAX * MPAD];
__device__ float g_logits[PMAX];

// ---------------------------------------------------------------------------
// FP32 SGEMM screen: sim[p][n] = sum_k A[p][k] * B[n][k]   (UNCHANGED)
// ---------------------------------------------------------------------------
__global__ __launch_bounds__(256, 2)
void gemm_kernel(const float* __restrict__ A, const float* __restrict__ B,
                 int P, int M) {
    __shared__ float As[2][16][128];
    __shared__ float Bs[2][16][128];

    const int tid = threadIdx.x;
    const int bm  = blockIdx.y * 128;
    const int bn  = blockIdx.x * 128;
    const int tx  = tid & 15;
    const int ty  = tid >> 4;
    const int lr  = tid >> 2;
    const int lc  = (tid & 3) << 2;

    const float* Aptr = A + (size_t)(bm + lr) * D + lc;
    const int n0 = bn + lr;
    const int n1 = bn + lr + 64;

    float4 ra0, ra1, rb0, rb1;
    const float4 fz = make_float4(0.f, 0.f, 0.f, 0.f);

    ra0 = *(const float4*)(Aptr);
    ra1 = *(const float4*)(Aptr + (size_t)64 * D);
    rb0 = (n0 < M) ? *(const float4*)(B + (size_t)n0 * D + lc) : fz;
    rb1 = (n1 < M) ? *(const float4*)(B + (size_t)n1 * D + lc) : fz;

    As[0][lc+0][lr]    = ra0.x; As[0][lc+1][lr]    = ra0.y;
    As[0][lc+2][lr]    = ra0.z; As[0][lc+3][lr]    = ra0.w;
    As[0][lc+0][lr+64] = ra1.x; As[0][lc+1][lr+64] = ra1.y;
    As[0][lc+2][lr+64] = ra1.z; As[0][lc+3][lr+64] = ra1.w;
    Bs[0][lc+0][lr]    = rb0.x; Bs[0][lc+1][lr]    = rb0.y;
    Bs[0][lc+2][lr]    = rb0.z; Bs[0][lc+3][lr]    = rb0.w;
    Bs[0][lc+0][lr+64] = rb1.x; Bs[0][lc+1][lr+64] = rb1.y;
    Bs[0][lc+2][lr+64] = rb1.z; Bs[0][lc+3][lr+64] = rb1.w;
    __syncthreads();

    float acc[8][8];
    #pragma unroll
    for (int i = 0; i < 8; ++i)
        #pragma unroll
        for (int j = 0; j < 8; ++j) acc[i][j] = 0.f;

    #pragma unroll
    for (int kt = 0; kt < 8; ++kt) {
        const int cur = kt & 1;
        if (kt < 7) {
            const int k0 = (kt + 1) * 16;
            ra0 = *(const float4*)(Aptr + k0);
            ra1 = *(const float4*)(Aptr + (size_t)64 * D + k0);
            rb0 = (n0 < M) ? *(const float4*)(B + (size_t)n0 * D + lc + k0) : fz;
            rb1 = (n1 < M) ? *(const float4*)(B + (size_t)n1 * D + lc + k0) : fz;
        }
        #pragma unroll
        for (int k = 0; k < 16; ++k) {
            float a[8], b[8];
            *(float4*)(a)     = *(const float4*)&As[cur][k][ty * 8];
            *(float4*)(a + 4) = *(const float4*)&As[cur][k][ty * 8 + 4];
            *(float4*)(b)     = *(const float4*)&Bs[cur][k][tx * 8];
            *(float4*)(b + 4) = *(const float4*)&Bs[cur][k][tx * 8 + 4];
            #pragma unroll
            for (int i = 0; i < 8; ++i)
                #pragma unroll
                for (int j = 0; j < 8; ++j)
                    acc[i][j] = fmaf(a[i], b[j], acc[i][j]);
        }
        if (kt < 7) {
            const int nxt = cur ^ 1;
            As[nxt][lc+0][lr]    = ra0.x; As[nxt][lc+1][lr]    = ra0.y;
            As[nxt][lc+2][lr]    = ra0.z; As[nxt][lc+3][lr]    = ra0.w;
            As[nxt][lc+0][lr+64] = ra1.x; As[nxt][lc+1][lr+64] = ra1.y;
            As[nxt][lc+2][lr+64] = ra1.z; As[nxt][lc+3][lr+64] = ra1.w;
            Bs[nxt][lc+0][lr]    = rb0.x; Bs[nxt][lc+1][lr]    = rb0.y;
            Bs[nxt][lc+2][lr]    = rb0.z; Bs[nxt][lc+3][lr]    = rb0.w;
            Bs[nxt][lc+0][lr+64] = rb1.x; Bs[nxt][lc+1][lr+64] = rb1.y;
            Bs[nxt][lc+2][lr+64] = rb1.z; Bs[nxt][lc+3][lr+64] = rb1.w;
            __syncthreads();
        }
    }

    #pragma unroll
    for (int i = 0; i < 8; ++i) {
        float* dst = g_sim + (size_t)(bm + ty * 8 + i) * MPAD + bn + tx * 8;
        *(float4*)(dst)     = make_float4(acc[i][0], acc[i][1], acc[i][2], acc[i][3]);
        *(float4*)(dst + 4) = make_float4(acc[i][4], acc[i][5], acc[i][6], acc[i][7]);
    }
}

// ---------------------------------------------------------------------------
// BF16x9 helpers
// ---------------------------------------------------------------------------
__device__ __forceinline__ float bf16_rn(float f) {
    unsigned int u = __float_as_uint(f);
    u = (u + 0x7FFFu + ((u >> 16) & 1u)) & 0xFFFF0000u;
    return __uint_as_float(u);
}
__device__ __forceinline__ void bf16_split3(float f, float& h, float& m, float& l) {
    h = bf16_rn(f);
    const float r1 = __fsub_rn(f, h);
    m = bf16_rn(r1);
    l = bf16_rn(__fsub_rn(r1, m));
}

__device__ __forceinline__ unsigned int fkey(float f) {
    unsigned int u = __float_as_uint(f);
    return (u & 0x80000000u) ? ~u : (u | 0x80000000u);
}
__device__ __forceinline__ float inv_fkey(unsigned int k) {
    unsigned int u = (k & 0x80000000u) ? (k & 0x7FFFFFFFu) : ~k;
    return __uint_as_float(u);
}

// ---------------------------------------------------------------------------
// Per-row top-K selection (one CTA per row)
// VALIDATED recipe (R12 pass): screen fp32 sim -> candidates -> bf16x9
// refine (exact f64 pass sums, one RN cast each, DESCENDING f32 combine
// hh,hm,hl,mh,mm,ml,lh,lm,ll) -> iterative argmax.
// NEW (perf only, bit-identical output): exact 50th-largest SCREEN key among
// candidates via bitwise search; refine only candidates with screen value
// >= v50 - 0.0625 (margin >=100x the |screen-refined| bound ~5e-4). Others
// get key 0 — they could never win one of the 50 argmax slots anyway.
// ---------------------------------------------------------------------------
__global__ __launch_bounds__(256)
void select_kernel(const float* __restrict__ X, const float* __restrict__ B,
                   int P, int M, float* __restrict__ out) {
    __shared__ unsigned int s_keys[CAP];
    __shared__ int s_idx[CAP];
    __shared__ double sxd[3][D];  // A splits in f64: [0]=h, [1]=m, [2]=l
    __shared__ int s_cnt;
    __shared__ int s_tot;
    __shared__ unsigned long long s_red[256];

    const int p   = blockIdx.x;
    const int tid = threadIdx.x;
    const float* __restrict__ row = g_sim + (size_t)p * MPAD;

    if (tid < D) {
        float h, m, l;
        bf16_split3(X[(size_t)p * D + tid], h, m, l);
        sxd[0][tid] = (double)h; sxd[1][tid] = (double)m; sxd[2][tid] = (double)l;
    }

    // --- deterministic strided sample ---
    int step = M / NSAMP; if (step < 1) step = 1;
    unsigned int samp[NSAMP / 256];
    #pragma unroll
    for (int t = 0; t < NSAMP / 256; ++t) {
        long long j = (long long)(tid + t * 256) * step;
        if (j >= M) j = M - 1;
        samp[t] = fkey(row[j]);
    }

    // --- binary search for the sample's TOPK-th largest screen key ---
    unsigned int thr = 0u;
    for (int bit = 31; bit >= 0; --bit) {
        const unsigned int cand = thr | (1u << bit);
        if (tid == 0) s_tot = 0;
        __syncthreads();
        int local = 0;
        #pragma unroll
        for (int t = 0; t < NSAMP / 256; ++t) local += (samp[t] >= cand);
        #pragma unroll
        for (int o = 16; o; o >>= 1) local += __shfl_down_sync(0xffffffffu, local, o);
        if ((tid & 31) == 0) atomicAdd(&s_tot, local);
        __syncthreads();
        if (s_tot >= TOPK) thr = cand;
        __syncthreads();
    }

    // --- collect candidates ---
    if (tid == 0) s_cnt = 0;
    __syncthreads();
    for (int n = tid; n < M; n += 256) {
        const unsigned int k = fkey(row[n]);
        if (k >= thr) {
            const int pos = atomicAdd(&s_cnt, 1);
            if (pos < CAP) { s_keys[pos] = k; s_idx[pos] = n; }
        }
    }
    __syncthreads();
    const int cnt = (s_cnt < CAP) ? s_cnt : CAP;

    // --- exact 50th-largest SCREEN key among candidates (bitwise search) ---
    unsigned int thr50 = 0u;
    for (int bit = 31; bit >= 0; --bit) {
        const unsigned int cand = thr50 | (1u << bit);
        if (tid == 0) s_tot = 0;
        __syncthreads();
        int local = 0;
        for (int i = tid; i < cnt; i += 256) local += (s_keys[i] >= cand);
        #pragma unroll
        for (int o = 16; o; o >>= 1) local += __shfl_down_sync(0xffffffffu, local, o);
        if ((tid & 31) == 0) atomicAdd(&s_tot, local);
        __syncthreads();
        if (s_tot >= TOPK) thr50 = cand;
        __syncthreads();
    }
    // gate: refine only candidates with screen value >= v50 - margin
    const unsigned int gkey = fkey(inv_fkey(thr50) - 0.0625f);

    // --- refine (gated): bf16x9, exact f64 pass sums + descending combine ---
    for (int i = tid; i < cnt; i += 256) {
        if (s_keys[i] < gkey) { s_keys[i] = 0u; continue; }
        const float* __restrict__ brow = B + (size_t)s_idx[i] * D;
        double S[9];
        #pragma unroll
        for (int q = 0; q < 9; ++q) S[q] = 0.0;

        #pragma unroll 4
        for (int kk = 0; kk < D; ++kk) {
            float bh, bm, bl;
            bf16_split3(__ldg(&brow[kk]), bh, bm, bl);
            const double dbh = (double)bh, dbm = (double)bm, dbl_ = (double)bl;
            const double xh = sxd[0][kk];
            const double xm = sxd[1][kk];
            const double xl = sxd[2][kk];
            S[0] = fma(xh, dbh,  S[0]);   // hh
            S[1] = fma(xh, dbm,  S[1]);   // hm
            S[2] = fma(xh, dbl_, S[2]);   // hl
            S[3] = fma(xm, dbh,  S[3]);   // mh
            S[4] = fma(xm, dbm,  S[4]);   // mm
            S[5] = fma(xm, dbl_, S[5]);   // ml
            S[6] = fma(xl, dbh,  S[6]);   // lh
            S[7] = fma(xl, dbm,  S[7]);   // lm
            S[8] = fma(xl, dbl_, S[8]);   // ll
        }
        // one RN per pass (f64 -> f32 cast), then descending combine
        float acc = (float)S[0];                      // hh
        acc = __fadd_rn(acc, (float)S[1]);            // hm
        acc = __fadd_rn(acc, (float)S[2]);            // hl
        acc = __fadd_rn(acc, (float)S[3]);            // mh
        acc = __fadd_rn(acc, (float)S[4]);            // mm
        acc = __fadd_rn(acc, (float)S[5]);            // ml
        acc = __fadd_rn(acc, (float)S[6]);            // lh
        acc = __fadd_rn(acc, (float)S[7]);            // lm
        acc = __fadd_rn(acc, (float)S[8]);            // ll
        s_keys[i] = fkey(acc);
    }
    __syncthreads();

    // --- iterative argmax: (value desc, index asc) matches stable top_k ---
    for (int k = 0; k < TOPK; ++k) {
        unsigned long long best = 0ull;
        for (int i = tid; i < cnt; i += 256) {
            const unsigned long long v =
                ((unsigned long long)s_keys[i] << 32) | (unsigned int)(~s_idx[i]);
            if (v > best) best = v;
        }
        s_red[tid] = best;
        __syncthreads();
        #pragma unroll
        for (int s = 128; s > 0; s >>= 1) {
            if (tid < s && s_red[tid + s] > s_red[tid]) s_red[tid] = s_red[tid + s];
            __syncthreads();
        }
        const unsigned long long w = s_red[0];
        for (int i = tid; i < cnt; i += 256) {
            const unsigned long long v =
                ((unsigned long long)s_keys[i] << 32) | (unsigned int)(~s_idx[i]);
            if (v == w) s_keys[i] = 0u;
        }
        if (tid == 0) {
            const int idx = (int)(~(unsigned int)w);
            out[(size_t)p * TOPK + k] = (float)idx;
            out[(size_t)P * TOPK + (size_t)p * TOPK + k] = (float)p;
        }
        __syncthreads();
    }
}

// ---------------------------------------------------------------------------
// Pooling: logits = relu(X @ W1 + b1) @ W2 + b2
// ---------------------------------------------------------------------------
__global__ __launch_bounds__(256)
void logits_kernel(const float* __restrict__ X, const float* __restrict__ W1,
                   const float* __restrict__ b1, const float* __restrict__ W2,
                   const float* __restrict__ b2, int P) {
    __shared__ float sx[16][128];
    const int tid = threadIdx.x;
    const int p0  = blockIdx.x * 16;

    for (int i = tid; i < 16 * 128 && p0 * 128 + i < P * 128; i += 256)
        sx[i / 128][i % 128] = X[(size_t)p0 * 128 + i];
    __syncthreads();

    const int warp = tid >> 5, lane = tid & 31;
    for (int pi = warp; pi < 16 && p0 + pi < P; pi += 8) {
        float h0 = b1[lane], h1 = b1[lane + 32];
        const float* x = sx[pi];
        #pragma unroll
        for (int i = 0; i < 128; ++i) {
            const float xi = x[i];
            h0 = fmaf(xi, W1[i * HID + lane],      h0);
            h1 = fmaf(xi, W1[i * HID + lane + 32], h1);
        }
        float v = fmaxf(h0, 0.f) * W2[lane] + fmaxf(h1, 0.f) * W2[lane + 32];
        #pragma unroll
        for (int o = 16; o; o >>= 1) v += __shfl_down_sync(0xffffffffu, v, o);
        if (lane == 0) g_logits[p0 + pi] = v + b2[0];
    }
}

// Softmax over patches + weighted sum + L2 normalize (single CTA)
__global__ __launch_bounds__(256)
void pool_kernel(const float* __restrict__ X, int P, float* __restrict__ outg) {
    __shared__ float sw[PMAX];
    __shared__ float sg[128];
    __shared__ float sred[256];
    const int tid = threadIdx.x;

    float m = -3.4e38f;
    for (int p = tid; p < P; p += 256) m = fmaxf(m, g_logits[p]);
    sred[tid] = m; __syncthreads();
    #pragma unroll
    for (int s = 128; s > 0; s >>= 1) {
        if (tid < s) sred[tid] = fmaxf(sred[tid], sred[tid + s]);
        __syncthreads();
    }
    const float mx = sred[0]; __syncthreads();

    float lsum = 0.f;
    for (int p = tid; p < P; p += 256) {
        const float e = expf(g_logits[p] - mx);
        sw[p] = e; lsum += e;
    }
    sred[tid] = lsum; __syncthreads();
    #pragma unroll
    for (int s = 128; s > 0; s >>= 1) {
        if (tid < s) sred[tid] += sred[tid + s];
        __syncthreads();
    }
    const float tot = sred[0]; __syncthreads();

    float g = 0.f;
    if (tid < 128) {
        // 4 independent accumulators -> MLP=4 on the X loads
        float g0 = 0.f, g1 = 0.f, g2 = 0.f, g3 = 0.f;
        int p = 0;
        for (; p + 3 < P; p += 4) {
            g0 = fmaf(sw[p+0], X[(size_t)(p+0) * D + tid], g0);
            g1 = fmaf(sw[p+1], X[(size_t)(p+1) * D + tid], g1);
            g2 = fmaf(sw[p+2], X[(size_t)(p+2) * D + tid], g2);
            g3 = fmaf(sw[p+3], X[(size_t)(p+3) * D + tid], g3);
        }
        for (; p < P; ++p) g0 = fmaf(sw[p], X[(size_t)p * D + tid], g0);
        g = ((g0 + g1) + (g2 + g3)) / tot;
        sg[tid]  = g;
        sred[tid] = g * g;
    } else {
        sred[tid] = 0.f;
    }
    __syncthreads();
    #pragma unroll
    for (int s = 128; s > 0; s >>= 1) {
        if (tid < s) sred[tid] += sred[tid + s];
        __syncthreads();
    }
    const float nrm = sqrtf(sred[0]);
    if (tid < 128) outg[tid] = sg[tid] / fmaxf(nrm, 1e-12f);
}

// ---------------------------------------------------------------------------
extern "C" void kernel_launch(void* const* d_in, const int* in_sizes, int n_in,
                              void* d_out, int out_size) {
    const float* X  = (const float*)d_in[0];
    const float* B  = (const float*)d_in[1];
    const float* W1 = (const float*)d_in[2];
    const float* b1 = (const float*)d_in[3];
    const float* W2 = (const float*)d_in[4];
    const float* b2 = (const float*)d_in[5];
    float* out = (float*)d_out;

    const int P = in_sizes[0] / D;
    const int M = in_sizes[1] / D;

    dim3 ggrid((M + 127) / 128, P / 128);
    gemm_kernel<<<ggrid, 256>>>(X, B, P, M);
    select_kernel<<<P, 256>>>(X, B, P, M, out);
    logits_kernel<<<(P + 15) / 16, 256>>>(X, W1, b1, W2, b2, P);
    pool_kernel<<<1, 256>>>(X, P, out + (size_t)2 * P * TOPK);
}

// round 15
// speedup vs baseline: 1.5175x; 1.2180x over previous
#include <cuda_runtime.h>
#include <cuda_bf16.h>
#include <cstdint>
#include <cstddef>

#define D     128
#define HID   64
#define TOPK  50
#define PMAX  2048
#define MPAD  100096   /* 782 * 128 */
#define NSAMP 8192
#define CAP   4096
#define SORTN 1024

// Scratch (device globals — no runtime allocation allowed)
__device__ float g_sim[(size_t)PMAX * MPAD];
__device__ float g_logits[PMAX];
__device__ __nv_bfloat16 g_Bb[(size_t)MPAD * D];
__device__ __nv_bfloat16 g_Xb[(size_t)PMAX * D];

// ---------------------------------------------------------------------------
// Convert inputs to bf16 (screen precision); zero-pad B rows beyond M.
// ---------------------------------------------------------------------------
__global__ __launch_bounds__(256)
void convert_kernel(const float* __restrict__ X, const float* __restrict__ Bsrc,
                    int P, int M) {
    const size_t stride = (size_t)gridDim.x * 256;
    const size_t i0 = (size_t)blockIdx.x * 256 + threadIdx.x;
    const size_t totB = (size_t)MPAD * D;
    for (size_t t = i0; t < totB; t += stride) {
        const int n = (int)(t >> 7);
        float v = (n < M) ? Bsrc[t] : 0.f;
        g_Bb[t] = __float2bfloat16_rn(v);
    }
    const size_t totX = (size_t)P * D;
    for (size_t t = i0; t < totX; t += stride)
        g_Xb[t] = __float2bfloat16_rn(X[t]);
}

// ---------------------------------------------------------------------------
// BF16 tensor-core screen GEMM: sim[p][n] = sum_k Xb[p][k]*Bb[n][k], f32 accum
// 128x128 tile per CTA, mma.sync m16n8k16.
// Both A[m][k] and B[n][k] are k-contiguous => BOTH use NON-trans ldmatrix:
// thread t then holds (row t/4, k-pair (t%4)*2) — exactly the A and B
// fragment layouts for row.col mma.
// ---------------------------------------------------------------------------
__global__ __launch_bounds__(256, 2)
void mma_gemm_kernel(int P, int M) {
    __shared__ __align__(16) unsigned short As[128 * 64];
    __shared__ __align__(16) unsigned short Bs[128 * 64];

    const int tid = threadIdx.x;
    const int bn  = blockIdx.x * 128;
    const int bm  = blockIdx.y * 128;
    const int wid  = tid >> 5, lane = tid & 31;
    const int warpM = wid >> 1, warpN = wid & 1;
    const int mW = warpM * 32, nW = warpN * 64;

    float acc[2][8][4];
    #pragma unroll
    for (int mi = 0; mi < 2; ++mi)
        #pragma unroll
        for (int nj = 0; nj < 8; ++nj)
            #pragma unroll
            for (int q = 0; q < 4; ++q) acc[mi][nj][q] = 0.f;

    const unsigned aBase = (unsigned)__cvta_generic_to_shared(As);
    const unsigned bBase = (unsigned)__cvta_generic_to_shared(Bs);

    #pragma unroll
    for (int kh = 0; kh < 2; ++kh) {
        // load half-tiles (8 chunks of 16B per row, swizzled chunk = c ^ (row&7))
        #pragma unroll
        for (int i = 0; i < 4; ++i) {
            const int idx = tid + i * 256;      // 0..1023
            const int row = idx >> 3, c = idx & 7;
            *(uint4*)(As + (size_t)((row << 3) + (c ^ (row & 7))) * 8) =
                *(const uint4*)(g_Xb + (((size_t)(bm + row)) << 7) + (size_t)kh * 64 + (c << 3));
            *(uint4*)(Bs + (size_t)((row << 3) + (c ^ (row & 7))) * 8) =
                *(const uint4*)(g_Bb + (((size_t)(bn + row)) << 7) + (size_t)kh * 64 + (c << 3));
        }
        __syncthreads();

        #pragma unroll
        for (int ks = 0; ks < 4; ++ks) {
            // A fragments (2 m16k16 per warp), non-trans x4
            unsigned a[2][4];
            #pragma unroll
            for (int mi = 0; mi < 2; ++mi) {
                const int row = mW + mi * 16 + (lane & 7) + ((lane >> 3) & 1) * 8;
                const int c   = ks * 2 + (lane >> 4);
                const unsigned addr = aBase + (unsigned)(((row << 3) + (c ^ (row & 7))) * 16);
                asm volatile("ldmatrix.sync.aligned.m8n8.x4.shared.b16 {%0,%1,%2,%3}, [%4];"
                    : "=r"(a[mi][0]), "=r"(a[mi][1]), "=r"(a[mi][2]), "=r"(a[mi][3])
                    : "r"(addr));
            }
            // B fragments (8 n8k16 per warp), non-trans x4:
            // r0=(n0-7,k0-7) r1=(n8-15,k0-7) r2=(n0-7,k8-15) r3=(n8-15,k8-15)
            unsigned bf[8][2];
            #pragma unroll
            for (int g = 0; g < 4; ++g) {
                const int row = nW + g * 16 + (lane & 7) + ((lane >> 3) & 1) * 8;
                const int c   = ks * 2 + (lane >> 4);
                const unsigned addr = bBase + (unsigned)(((row << 3) + (c ^ (row & 7))) * 16);
                unsigned r0, r1, r2, r3;
                asm volatile("ldmatrix.sync.aligned.m8n8.x4.shared.b16 {%0,%1,%2,%3}, [%4];"
                    : "=r"(r0), "=r"(r1), "=r"(r2), "=r"(r3) : "r"(addr));
                bf[g*2][0]   = r0; bf[g*2][1]   = r2;   // n-block g*16+0..7 : k0-7, k8-15
                bf[g*2+1][0] = r1; bf[g*2+1][1] = r3;   // n-block g*16+8..15
            }
            #pragma unroll
            for (int mi = 0; mi < 2; ++mi)
                #pragma unroll
                for (int nj = 0; nj < 8; ++nj)
                    asm volatile("mma.sync.aligned.m16n8k16.row.col.f32.bf16.bf16.f32 "
                        "{%0,%1,%2,%3}, {%4,%5,%6,%7}, {%8,%9}, {%0,%1,%2,%3};"
                        : "+f"(acc[mi][nj][0]), "+f"(acc[mi][nj][1]),
                          "+f"(acc[mi][nj][2]), "+f"(acc[mi][nj][3])
                        : "r"(a[mi][0]), "r"(a[mi][1]), "r"(a[mi][2]), "r"(a[mi][3]),
                          "r"(bf[nj][0]), "r"(bf[nj][1]));
        }
        __syncthreads();
    }

    // epilogue: c0,c1 -> (row lane/4, col (lane%4)*2 +0,1); c2,c3 -> row+8
    #pragma unroll
    for (int mi = 0; mi < 2; ++mi) {
        const int r0 = bm + mW + mi * 16 + (lane >> 2);
        const int c0 = bn + nW + (lane & 3) * 2;
        #pragma unroll
        for (int nj = 0; nj < 8; ++nj) {
            float* d0 = g_sim + (size_t)r0 * MPAD + c0 + nj * 8;
            *(float2*)d0 = make_float2(acc[mi][nj][0], acc[mi][nj][1]);
            float* d1 = d0 + (size_t)8 * MPAD;
            *(float2*)d1 = make_float2(acc[mi][nj][2], acc[mi][nj][3]);
        }
    }
}

// ---------------------------------------------------------------------------
// BF16x9 helpers
// ---------------------------------------------------------------------------
__device__ __forceinline__ float bf16_rn(float f) {
    unsigned int u = __float_as_uint(f);
    u = (u + 0x7FFFu + ((u >> 16) & 1u)) & 0xFFFF0000u;
    return __uint_as_float(u);
}
__device__ __forceinline__ void bf16_split3(float f, float& h, float& m, float& l) {
    h = bf16_rn(f);
    const float r1 = __fsub_rn(f, h);
    m = bf16_rn(r1);
    l = bf16_rn(__fsub_rn(r1, m));
}
__device__ __forceinline__ unsigned int fkey(float f) {
    unsigned int u = __float_as_uint(f);
    return (u & 0x80000000u) ? ~u : (u | 0x80000000u);
}
__device__ __forceinline__ float inv_fkey(unsigned int k) {
    unsigned int u = (k & 0x80000000u) ? (k & 0x7FFFFFFFu) : ~k;
    return __uint_as_float(u);
}

// ---------------------------------------------------------------------------
// Per-row top-K selection (one CTA per row)
// VALIDATED ranking recipe (R12/R13): bf16x9 refine (exact f64 pass sums,
// one RN cast each, DESCENDING f32 combine hh,hm,hl,mh,mm,ml,lh,lm,ll).
// Screen is bf16 (noise sigma ~0.034, worst ~0.2) => gate margin 1.0.
// Finish: compact gate-passers and bitonic-sort (order-equivalent to argmax).
// ---------------------------------------------------------------------------
__global__ __launch_bounds__(256)
void select_kernel(const float* __restrict__ X, const float* __restrict__ B,
                   int P, int M, float* __restrict__ out) {
    __shared__ unsigned int s_keys[CAP];
    __shared__ int s_idx[CAP];
    __shared__ double sxd[3][D];
    __shared__ unsigned long long s_sort[SORTN];
    __shared__ int s_cnt;
    __shared__ int s_tot;
    __shared__ int s_m;

    const int p   = blockIdx.x;
    const int tid = threadIdx.x;
    const float* __restrict__ row = g_sim + (size_t)p * MPAD;

    if (tid < D) {
        float h, m, l;
        bf16_split3(X[(size_t)p * D + tid], h, m, l);
        sxd[0][tid] = (double)h; sxd[1][tid] = (double)m; sxd[2][tid] = (double)l;
    }

    // --- deterministic strided sample ---
    int step = M / NSAMP; if (step < 1) step = 1;
    unsigned int samp[NSAMP / 256];
    #pragma unroll
    for (int t = 0; t < NSAMP / 256; ++t) {
        long long j = (long long)(tid + t * 256) * step;
        if (j >= M) j = M - 1;
        samp[t] = fkey(row[j]);
    }

    // --- binary search for the sample's TOPK-th largest screen key ---
    unsigned int thr = 0u;
    for (int bit = 31; bit >= 0; --bit) {
        const unsigned int cand = thr | (1u << bit);
        if (tid == 0) s_tot = 0;
        __syncthreads();
        int local = 0;
        #pragma unroll
        for (int t = 0; t < NSAMP / 256; ++t) local += (samp[t] >= cand);
        #pragma unroll
        for (int o = 16; o; o >>= 1) local += __shfl_down_sync(0xffffffffu, local, o);
        if ((tid & 31) == 0) atomicAdd(&s_tot, local);
        __syncthreads();
        if (s_tot >= TOPK) thr = cand;
        __syncthreads();
    }

    // --- collect candidates ---
    if (tid == 0) s_cnt = 0;
    __syncthreads();
    for (int n = tid; n < M; n += 256) {
        const unsigned int k = fkey(row[n]);
        if (k >= thr) {
            const int pos = atomicAdd(&s_cnt, 1);
            if (pos < CAP) { s_keys[pos] = k; s_idx[pos] = n; }
        }
    }
    __syncthreads();
    const int cnt = (s_cnt < CAP) ? s_cnt : CAP;

    // --- exact 50th-largest SCREEN key among candidates ---
    unsigned int thr50 = 0u;
    for (int bit = 31; bit >= 0; --bit) {
        const unsigned int cand = thr50 | (1u << bit);
        if (tid == 0) s_tot = 0;
        __syncthreads();
        int local = 0;
        for (int i = tid; i < cnt; i += 256) local += (s_keys[i] >= cand);
        #pragma unroll
        for (int o = 16; o; o >>= 1) local += __shfl_down_sync(0xffffffffu, local, o);
        if ((tid & 31) == 0) atomicAdd(&s_tot, local);
        __syncthreads();
        if (s_tot >= TOPK) thr50 = cand;
        __syncthreads();
    }
    // gate margin 1.0 (>=3x worst-case bf16 screen divergence)
    const unsigned int gkey = fkey(inv_fkey(thr50) - 1.0f);

    // --- refine (gated): bf16x9, exact f64 pass sums + descending combine ---
    for (int i = tid; i < cnt; i += 256) {
        if (s_keys[i] < gkey) { s_keys[i] = 0u; continue; }
        const float* __restrict__ brow = B + (size_t)s_idx[i] * D;
        double S[9];
        #pragma unroll
        for (int q = 0; q < 9; ++q) S[q] = 0.0;

        #pragma unroll 4
        for (int kk = 0; kk < D; ++kk) {
            float bh, bm, bl;
            bf16_split3(__ldg(&brow[kk]), bh, bm, bl);
            const double dbh = (double)bh, dbm = (double)bm, dbl_ = (double)bl;
            const double xh = sxd[0][kk];
            const double xm = sxd[1][kk];
            const double xl = sxd[2][kk];
            S[0] = fma(xh, dbh,  S[0]);
            S[1] = fma(xh, dbm,  S[1]);
            S[2] = fma(xh, dbl_, S[2]);
            S[3] = fma(xm, dbh,  S[3]);
            S[4] = fma(xm, dbm,  S[4]);
            S[5] = fma(xm, dbl_, S[5]);
            S[6] = fma(xl, dbh,  S[6]);
            S[7] = fma(xl, dbm,  S[7]);
            S[8] = fma(xl, dbl_, S[8]);
        }
        float acc = (float)S[0];
        acc = __fadd_rn(acc, (float)S[1]);
        acc = __fadd_rn(acc, (float)S[2]);
        acc = __fadd_rn(acc, (float)S[3]);
        acc = __fadd_rn(acc, (float)S[4]);
        acc = __fadd_rn(acc, (float)S[5]);
        acc = __fadd_rn(acc, (float)S[6]);
        acc = __fadd_rn(acc, (float)S[7]);
        acc = __fadd_rn(acc, (float)S[8]);
        s_keys[i] = fkey(acc);
    }
    __syncthreads();

    // --- compact gate-passers, bitonic sort descending, emit top-50 ---
    if (tid == 0) s_m = 0;
    for (int i = tid; i < SORTN; i += 256) s_sort[i] = 0ull;
    __syncthreads();
    for (int i = tid; i < cnt; i += 256) {
        if (s_keys[i]) {
            const int pos = atomicAdd(&s_m, 1);
            if (pos < SORTN)
                s_sort[pos] = ((unsigned long long)s_keys[i] << 32)
                            | (unsigned int)(~s_idx[i]);
        }
    }
    __syncthreads();
    for (int k2 = 2; k2 <= SORTN; k2 <<= 1) {
        for (int j2 = k2 >> 1; j2 > 0; j2 >>= 1) {
            for (int i = tid; i < SORTN; i += 256) {
                const int ixj = i ^ j2;
                if (ixj > i) {
                    const unsigned long long x = s_sort[i], y = s_sort[ixj];
                    const bool up = ((i & k2) == 0);
                    if (up ? (x < y) : (x > y)) { s_sort[i] = y; s_sort[ixj] = x; }
                }
            }
            __syncthreads();
        }
    }
    if (tid < TOPK) {
        const unsigned long long w = s_sort[tid];
        const int idx = (int)(~(unsigned int)w);
        out[(size_t)p * TOPK + tid] = (float)idx;
        out[(size_t)P * TOPK + (size_t)p * TOPK + tid] = (float)p;
    }
}

// ---------------------------------------------------------------------------
// Pooling: logits = relu(X @ W1 + b1) @ W2 + b2
// ---------------------------------------------------------------------------
__global__ __launch_bounds__(256)
void logits_kernel(const float* __restrict__ X, const float* __restrict__ W1,
                   const float* __restrict__ b1, const float* __restrict__ W2,
                   const float* __restrict__ b2, int P) {
    __shared__ float sx[16][128];
    const int tid = threadIdx.x;
    const int p0  = blockIdx.x * 16;

    for (int i = tid; i < 16 * 128 && p0 * 128 + i < P * 128; i += 256)
        sx[i / 128][i % 128] = X[(size_t)p0 * 128 + i];
    __syncthreads();

    const int warp = tid >> 5, lane = tid & 31;
    for (int pi = warp; pi < 16 && p0 + pi < P; pi += 8) {
        float h0 = b1[lane], h1 = b1[lane + 32];
        const float* x = sx[pi];
        #pragma unroll
        for (int i = 0; i < 128; ++i) {
            const float xi = x[i];
            h0 = fmaf(xi, W1[i * HID + lane],      h0);
            h1 = fmaf(xi, W1[i * HID + lane + 32], h1);
        }
        float v = fmaxf(h0, 0.f) * W2[lane] + fmaxf(h1, 0.f) * W2[lane + 32];
        #pragma unroll
        for (int o = 16; o; o >>= 1) v += __shfl_down_sync(0xffffffffu, v, o);
        if (lane == 0) g_logits[p0 + pi] = v + b2[0];
    }
}

// Softmax over patches + weighted sum + L2 normalize (single CTA)
__global__ __launch_bounds__(256)
void pool_kernel(const float* __restrict__ X, int P, float* __restrict__ outg) {
    __shared__ float sw[PMAX];
    __shared__ float sg[128];
    __shared__ float sred[256];
    const int tid = threadIdx.x;

    float m = -3.4e38f;
    for (int p = tid; p < P; p += 256) m = fmaxf(m, g_logits[p]);
    sred[tid] = m; __syncthreads();
    #pragma unroll
    for (int s = 128; s > 0; s >>= 1) {
        if (tid < s) sred[tid] = fmaxf(sred[tid], sred[tid + s]);
        __syncthreads();
    }
    const float mx = sred[0]; __syncthreads();

    float lsum = 0.f;
    for (int p = tid; p < P; p += 256) {
        const float e = expf(g_logits[p] - mx);
        sw[p] = e; lsum += e;
    }
    sred[tid] = lsum; __syncthreads();
    #pragma unroll
    for (int s = 128; s > 0; s >>= 1) {
        if (tid < s) sred[tid] += sred[tid + s];
        __syncthreads();
    }
    const float tot = sred[0]; __syncthreads();

    if (tid < 128) {
        float g0 = 0.f, g1 = 0.f, g2 = 0.f, g3 = 0.f;
        int p = 0;
        for (; p + 3 < P; p += 4) {
            g0 = fmaf(sw[p+0], X[(size_t)(p+0) * D + tid], g0);
            g1 = fmaf(sw[p+1], X[(size_t)(p+1) * D + tid], g1);
            g2 = fmaf(sw[p+2], X[(size_t)(p+2) * D + tid], g2);
            g3 = fmaf(sw[p+3], X[(size_t)(p+3) * D + tid], g3);
        }
        for (; p < P; ++p) g0 = fmaf(sw[p], X[(size_t)p * D + tid], g0);
        const float g = ((g0 + g1) + (g2 + g3)) / tot;
        sg[tid]  = g;
        sred[tid] = g * g;
    } else {
        sred[tid] = 0.f;
    }
    __syncthreads();
    #pragma unroll
    for (int s = 128; s > 0; s >>= 1) {
        if (tid < s) sred[tid] += sred[tid + s];
        __syncthreads();
    }
    const float nrm = sqrtf(sred[0]);
    if (tid < 128) outg[tid] = sg[tid] / fmaxf(nrm, 1e-12f);
}

// ---------------------------------------------------------------------------
extern "C" void kernel_launch(void* const* d_in, const int* in_sizes, int n_in,
                              void* d_out, int out_size) {
    const float* X  = (const float*)d_in[0];
    const float* B  = (const float*)d_in[1];
    const float* W1 = (const float*)d_in[2];
    const float* b1 = (const float*)d_in[3];
    const float* W2 = (const float*)d_in[4];
    const float* b2 = (const float*)d_in[5];
    float* out = (float*)d_out;

    const int P = in_sizes[0] / D;
    const int M = in_sizes[1] / D;

    convert_kernel<<<2048, 256>>>(X, B, P, M);
    dim3 ggrid((M + 127) / 128, P / 128);
    mma_gemm_kernel<<<ggrid, 256>>>(P, M);
    select_kernel<<<P, 256>>>(X, B, P, M, out);
    logits_kernel<<<(P + 15) / 16, 256>>>(X, W1, b1, W2, b2, P);
    pool_kernel<<<1, 256>>>(X, P, out + (size_t)2 * P * TOPK);
}